// round 12
// baseline (speedup 1.0000x reference)
#include <cuda_runtime.h>
#include <cuda_bf16.h>
#include <mma.h>

using namespace nvcuda;

#define MAXN 50000
#define MAXE 800000
#define NSM  148
#define SW   136          // padded smem row stride (bf16 elems)

// ---------------- scratch (device globals; no allocation allowed) ----------
__device__ float g_xl[MAXN * 128];
__device__ float g_xr[MAXN * 128];
__device__ float g_h [MAXN * 128];
__device__ int   g_deg[MAXN];
__device__ int   g_rowptr[MAXN + 1];
__device__ int   g_blocksum[64];
__device__ int   g_csr_src[MAXE];

// ================= CSR build (by dst) ======================================
__global__ void deg_zero(int n) {
    int i = blockIdx.x * blockDim.x + threadIdx.x;
    if (i < n) g_deg[i] = 0;
}

__global__ void deg_count(const int* __restrict__ ei, int E) {
    int i = blockIdx.x * blockDim.x + threadIdx.x;
    if (i < E) atomicAdd(&g_deg[__ldg(&ei[E + i])], 1);
}

__global__ void scan1(int n) {
    __shared__ int s[1024];
    int i = blockIdx.x * 1024 + threadIdx.x;
    int v = (i < n) ? g_deg[i] : 0;
    s[threadIdx.x] = v;
    __syncthreads();
    #pragma unroll
    for (int off = 1; off < 1024; off <<= 1) {
        int t = (threadIdx.x >= off) ? s[threadIdx.x - off] : 0;
        __syncthreads();
        s[threadIdx.x] += t;
        __syncthreads();
    }
    if (i < n) g_rowptr[i] = s[threadIdx.x] - v;
    if (threadIdx.x == 1023) g_blocksum[blockIdx.x] = s[1023];
}

__global__ void scan3(int n, int E, int nb) {
    __shared__ int bs[64];
    int tid = threadIdx.x;
    if (tid < 64) bs[tid] = (tid < nb) ? g_blocksum[tid] : 0;
    __syncthreads();
    #pragma unroll
    for (int off = 1; off < 64; off <<= 1) {
        int t = (tid < 64 && tid >= off) ? bs[tid - off] : 0;
        __syncthreads();
        if (tid < 64) bs[tid] += t;
        __syncthreads();
    }
    int i = blockIdx.x * blockDim.x + tid;
    if (i < n) {
        int b = i >> 10;
        int pre = (b == 0) ? 0 : bs[b - 1];
        g_rowptr[i] += pre;
        g_deg[i] = 0;
    }
    if (i == 0) g_rowptr[n] = E;
}

__global__ void scatter(const int* __restrict__ ei, int E) {
    int i = blockIdx.x * blockDim.x + threadIdx.x;
    if (i >= E) return;
    int s = __ldg(&ei[i]);
    int d = __ldg(&ei[E + i]);
    int pos = g_rowptr[d] + atomicAdd(&g_deg[d], 1);
    g_csr_src[pos] = s;
}

// ============ persistent dual GEMM, W register-resident (bf16 x3) ==========
// 148 blocks x 512 threads (16 warps). warp w: matrix m = w>>3
// (0: xl, 1: xr), strip = cols [(w&7)*16, +16). W frags in registers.
// Double-buffered A smem: ONE sync per 32-row chunk.
using fA = wmma::fragment<wmma::matrix_a, 16, 16, 16, __nv_bfloat16, wmma::row_major>;
using fB = wmma::fragment<wmma::matrix_b, 16, 16, 16, __nv_bfloat16, wmma::row_major>;
using fC = wmma::fragment<wmma::accumulator, 16, 16, 16, float>;

__device__ __forceinline__ void cvt4(float4 v, __nv_bfloat16* hi, __nv_bfloat16* lo) {
    __nv_bfloat16 h0 = __float2bfloat16(v.x);
    __nv_bfloat16 h1 = __float2bfloat16(v.y);
    __nv_bfloat16 h2 = __float2bfloat16(v.z);
    __nv_bfloat16 h3 = __float2bfloat16(v.w);
    hi[0] = h0; hi[1] = h1; hi[2] = h2; hi[3] = h3;
    lo[0] = __float2bfloat16(v.x - __bfloat162float(h0));
    lo[1] = __float2bfloat16(v.y - __bfloat162float(h1));
    lo[2] = __float2bfloat16(v.z - __bfloat162float(h2));
    lo[3] = __float2bfloat16(v.w - __bfloat162float(h3));
}

__global__ void __launch_bounds__(512, 1)
dual_gemm_wreg(const float* __restrict__ Aext,
               const float* __restrict__ Wl,
               const float* __restrict__ Wr,
               int useH, int n) {
    // union (34816B): W staging 128xSW bf16 (one-time)
    //                 then A double buffer: buf0 / buf1, each 2x32xSW bf16
    __shared__ __align__(16) unsigned char smem_u[34816];
    __nv_bfloat16* ws = (__nv_bfloat16*)smem_u;

    const float* A = useH ? g_h : Aext;
    const float* Wmat[2] = {Wl, Wr};
    int tid   = threadIdx.x;
    int warp  = tid >> 5;
    int mat   = warp >> 3;          // 0 = xl, 1 = xr
    int sbase = (warp & 7) * 16;    // this warp's 16-col strip

    // per-thread A slot: f = tid + t*512 -> row rA[t], col cA
    int r0A = tid >> 5,          cA = (tid & 31) * 4;
    int r1A = (tid + 512) >> 5;

    // ---- load W fragments into registers (4 staging passes) ----
    fB wf[2][8];                    // [part][k]
    #pragma unroll
    for (int m = 0; m < 2; ++m) {
        #pragma unroll
        for (int part = 0; part < 2; ++part) {
            __syncthreads();
            #pragma unroll
            for (int t = 0; t < 8; ++t) {
                int f  = tid + t * 512;
                int r  = f >> 5;
                int c4 = (f & 31) * 4;
                float4 v = *(const float4*)&Wmat[m][(size_t)r * 128 + c4];
                __nv_bfloat16 b0 = __float2bfloat16(v.x);
                __nv_bfloat16 b1 = __float2bfloat16(v.y);
                __nv_bfloat16 b2 = __float2bfloat16(v.z);
                __nv_bfloat16 b3 = __float2bfloat16(v.w);
                __nv_bfloat16* dst = &ws[r * SW + c4];
                if (part == 0) {
                    dst[0] = b0; dst[1] = b1; dst[2] = b2; dst[3] = b3;
                } else {
                    dst[0] = __float2bfloat16(v.x - __bfloat162float(b0));
                    dst[1] = __float2bfloat16(v.y - __bfloat162float(b1));
                    dst[2] = __float2bfloat16(v.z - __bfloat162float(b2));
                    dst[3] = __float2bfloat16(v.w - __bfloat162float(b3));
                }
            }
            __syncthreads();
            if (mat == m) {
                #pragma unroll
                for (int k = 0; k < 8; ++k)
                    wmma::load_matrix_sync(wf[part][k],
                                           &ws[k * 16 * SW + sbase], SW);
            }
        }
    }
    __syncthreads();                // W staging region now free for A buffers

    // A double buffers (bf16): buf b at offset b*17408 bytes
    __nv_bfloat16* abuf[2] = {(__nv_bfloat16*)smem_u,
                              (__nv_bfloat16*)(smem_u + 17408)};
    // within a buffer: hi at 0, lo at 32*SW

    float* C = mat ? g_xr : g_xl;
    int nchunks = (n + 31) >> 5;
    int stride  = gridDim.x;

    auto loadA = [&](int cc, float4& v0, float4& v1) {
        v0 = make_float4(0.f, 0.f, 0.f, 0.f);
        v1 = make_float4(0.f, 0.f, 0.f, 0.f);
        if (cc < nchunks) {
            int r = cc * 32;
            if (r + r0A < n) v0 = *(const float4*)&A[(size_t)(r + r0A) * 128 + cA];
            if (r + r1A < n) v1 = *(const float4*)&A[(size_t)(r + r1A) * 128 + cA];
        }
    };

    int c = blockIdx.x;
    float4 rv0, rv1;
    loadA(c, rv0, rv1);
    // stage first chunk into buf0
    if (c < nchunks) {
        __nv_bfloat16* hb = abuf[0];
        __nv_bfloat16* lb = abuf[0] + 32 * SW;
        cvt4(rv0, &hb[r0A * SW + cA], &lb[r0A * SW + cA]);
        cvt4(rv1, &hb[r1A * SW + cA], &lb[r1A * SW + cA]);
    }
    __syncthreads();
    loadA(c + stride, rv0, rv1);    // prefetch chunk c+stride

    int pb = 0;
    for (; c < nchunks; c += stride) {
        int cn = c + stride;
        // stage next chunk into the other buffer (its last readers were
        // fenced by the sync at the end of the previous iteration)
        if (cn < nchunks) {
            __nv_bfloat16* hb = abuf[pb ^ 1];
            __nv_bfloat16* lb = abuf[pb ^ 1] + 32 * SW;
            cvt4(rv0, &hb[r0A * SW + cA], &lb[r0A * SW + cA]);
            cvt4(rv1, &hb[r1A * SW + cA], &lb[r1A * SW + cA]);
        }
        loadA(cn + stride, rv0, rv1);   // global prefetch overlaps MMA

        __nv_bfloat16* ah_s = abuf[pb];
        __nv_bfloat16* al_s = abuf[pb] + 32 * SW;

        fC acc[2];
        wmma::fill_fragment(acc[0], 0.0f);
        wmma::fill_fragment(acc[1], 0.0f);

        #pragma unroll
        for (int k = 0; k < 8; ++k) {
            fA ah[2], al[2];
            wmma::load_matrix_sync(ah[0], &ah_s[0 * SW + k * 16], SW);
            wmma::load_matrix_sync(ah[1], &ah_s[16 * SW + k * 16], SW);
            wmma::load_matrix_sync(al[0], &al_s[0 * SW + k * 16], SW);
            wmma::load_matrix_sync(al[1], &al_s[16 * SW + k * 16], SW);
            wmma::mma_sync(acc[0], ah[0], wf[0][k], acc[0]);
            wmma::mma_sync(acc[1], ah[1], wf[0][k], acc[1]);
            wmma::mma_sync(acc[0], ah[0], wf[1][k], acc[0]);
            wmma::mma_sync(acc[1], ah[1], wf[1][k], acc[1]);
            wmma::mma_sync(acc[0], al[0], wf[0][k], acc[0]);
            wmma::mma_sync(acc[1], al[1], wf[0][k], acc[1]);
        }

        int row0 = c * 32;
        #pragma unroll
        for (int rt = 0; rt < 2; ++rt) {
            int wrow0 = row0 + rt * 16;
            if (wrow0 < n)
                wmma::store_matrix_sync(&C[(size_t)wrow0 * 128 + sbase],
                                        acc[rt], 128, wmma::mem_row_major);
        }
        __syncthreads();            // ONE sync per chunk
        pb ^= 1;
    }
}

// ================= fused GAT layer: warp per dst node ======================
__device__ __forceinline__ float edge_p(float4 l4, float4 r4, float4 a4) {
    float v0 = l4.x + r4.x; v0 = v0 > 0.f ? v0 : 0.2f * v0;
    float v1 = l4.y + r4.y; v1 = v1 > 0.f ? v1 : 0.2f * v1;
    float v2 = l4.z + r4.z; v2 = v2 > 0.f ? v2 : 0.2f * v2;
    float v3 = l4.w + r4.w; v3 = v3 > 0.f ? v3 : 0.2f * v3;
    float part = v0 * a4.x + v1 * a4.y + v2 * a4.z + v3 * a4.w;
    part += __shfl_xor_sync(0xffffffffu, part, 1);
    part += __shfl_xor_sync(0xffffffffu, part, 2);
    return __expf(part);
}

__global__ void gat_layer(const float* __restrict__ att,
                          const float* __restrict__ bias,
                          int doRelu, int n) {
    int d = blockIdx.x * 8 + (threadIdx.x >> 5);
    if (d >= n) return;
    int lane = threadIdx.x & 31;

    float4 a4 = *(const float4*)&att[lane * 4];
    float4 r4 = *(const float4*)&g_xr[(size_t)d * 128 + lane * 4];

    // self loop
    float4 l4 = *(const float4*)&g_xl[(size_t)d * 128 + lane * 4];
    float p = edge_p(l4, r4, a4);
    float4 acc = make_float4(p * l4.x, p * l4.y, p * l4.z, p * l4.w);
    float den = p;

    int e0  = g_rowptr[d];
    int end = g_rowptr[d + 1];

    // lane-parallel index preload: one coalesced load covers up to 32 edges
    int myidx = (e0 + lane < end) ? __ldg(&g_csr_src[e0 + lane]) : 0;
    int nb = end - e0; if (nb > 32) nb = 32;

    int j = 0;
    for (; j + 3 < nb; j += 4) {
        int s0 = __shfl_sync(0xffffffffu, myidx, j);
        int s1 = __shfl_sync(0xffffffffu, myidx, j + 1);
        int s2 = __shfl_sync(0xffffffffu, myidx, j + 2);
        int s3 = __shfl_sync(0xffffffffu, myidx, j + 3);
        float4 u0 = *(const float4*)&g_xl[(size_t)s0 * 128 + lane * 4];
        float4 u1 = *(const float4*)&g_xl[(size_t)s1 * 128 + lane * 4];
        float4 u2 = *(const float4*)&g_xl[(size_t)s2 * 128 + lane * 4];
        float4 u3 = *(const float4*)&g_xl[(size_t)s3 * 128 + lane * 4];
        float p0 = edge_p(u0, r4, a4);
        float p1 = edge_p(u1, r4, a4);
        float p2 = edge_p(u2, r4, a4);
        float p3 = edge_p(u3, r4, a4);
        acc.x += p0 * u0.x + p1 * u1.x + p2 * u2.x + p3 * u3.x;
        acc.y += p0 * u0.y + p1 * u1.y + p2 * u2.y + p3 * u3.y;
        acc.z += p0 * u0.z + p1 * u1.z + p2 * u2.z + p3 * u3.z;
        acc.w += p0 * u0.w + p1 * u1.w + p2 * u2.w + p3 * u3.w;
        den += p0 + p1 + p2 + p3;
    }
    for (; j < nb; ++j) {
        int s0 = __shfl_sync(0xffffffffu, myidx, j);
        float4 u0 = *(const float4*)&g_xl[(size_t)s0 * 128 + lane * 4];
        float p0 = edge_p(u0, r4, a4);
        acc.x += p0 * u0.x; acc.y += p0 * u0.y;
        acc.z += p0 * u0.z; acc.w += p0 * u0.w;
        den += p0;
    }
    // rare tail: degree > 32
    for (int e = e0 + 32; e < end; ++e) {
        int s0 = __ldg(&g_csr_src[e]);
        float4 u0 = *(const float4*)&g_xl[(size_t)s0 * 128 + lane * 4];
        float p0 = edge_p(u0, r4, a4);
        acc.x += p0 * u0.x; acc.y += p0 * u0.y;
        acc.z += p0 * u0.z; acc.w += p0 * u0.w;
        den += p0;
    }

    float inv = 1.0f / (den + 1e-16f);
    float4 b4 = bias ? *(const float4*)&bias[lane * 4]
                     : make_float4(0.f, 0.f, 0.f, 0.f);
    float4 o;
    o.x = acc.x * inv + b4.x;
    o.y = acc.y * inv + b4.y;
    o.z = acc.z * inv + b4.z;
    o.w = acc.w * inv + b4.w;
    if (doRelu) {
        o.x = o.x > 0.f ? o.x : 0.f;
        o.y = o.y > 0.f ? o.y : 0.f;
        o.z = o.z > 0.f ? o.z : 0.f;
        o.w = o.w > 0.f ? o.w : 0.f;
    }
    *(float4*)&g_h[(size_t)d * 128 + lane * 4] = o;
}

// ================= final fc: out = relu(g_h + b2) @ Wfc + bfc ==============
__global__ void fc_out(const float* __restrict__ Wfc,
                       const float* __restrict__ bfc,
                       const float* __restrict__ b2,
                       float* __restrict__ out, int n) {
    __shared__ float Ws[128 * 10];
    __shared__ float bs[10];
    __shared__ float b2s[128];
    for (int i = threadIdx.x; i < 1280; i += blockDim.x) Ws[i] = Wfc[i];
    if (threadIdx.x < 10)  bs[threadIdx.x]  = bfc[threadIdx.x];
    if (threadIdx.x < 128) b2s[threadIdx.x] = b2[threadIdx.x];
    __syncthreads();
    int idx = blockIdx.x * blockDim.x + threadIdx.x;
    if (idx >= n * 10) return;
    int node = idx / 10;
    int c    = idx % 10;
    const float* hrow = &g_h[(size_t)node * 128];
    float acc = bs[c];
    #pragma unroll
    for (int k = 0; k < 128; ++k) {
        float hv = hrow[k] + b2s[k];
        hv = hv > 0.f ? hv : 0.f;
        acc += hv * Ws[k * 10 + c];
    }
    out[idx] = acc;
}

// ================= launch ==================================================
extern "C" void kernel_launch(void* const* d_in, const int* in_sizes, int n_in,
                              void* d_out, int out_size) {
    const float* x    = (const float*)d_in[0];
    const int*   ei   = (const int*)  d_in[1];
    const float* Wl1  = (const float*)d_in[2];
    const float* Wr1  = (const float*)d_in[3];
    const float* att1 = (const float*)d_in[4];
    const float* b1   = (const float*)d_in[5];
    const float* Wl2  = (const float*)d_in[6];
    const float* Wr2  = (const float*)d_in[7];
    const float* att2 = (const float*)d_in[8];
    const float* b2   = (const float*)d_in[9];
    const float* Wfc  = (const float*)d_in[10];
    const float* bfc  = (const float*)d_in[11];
    float* out = (float*)d_out;

    int n = in_sizes[0] / 128;
    int E = in_sizes[1] / 2;

    int nb_scan    = (n + 1023) / 1024;
    int gat_blocks = (n + 7) / 8;
    int fc_blocks  = (n * 10 + 255) / 256;
    int e_blocks   = (E + 255) / 256;
    int n_blocks   = (n + 255) / 256;

    static int inited = 0;
    static cudaStream_t s_csr;
    static cudaEvent_t  ev_fork, ev_join;
    if (!inited) {
        cudaStreamCreateWithFlags(&s_csr, cudaStreamNonBlocking);
        cudaEventCreateWithFlags(&ev_fork, cudaEventDisableTiming);
        cudaEventCreateWithFlags(&ev_join, cudaEventDisableTiming);
        inited = 1;
    }

    // ---- fork: CSR build (s_csr)  ||  layer-1 GEMM (default) ----
    // (dual_gemm submitted 4th so the ncu slot profiles it)
    cudaEventRecord(ev_fork, 0);
    cudaStreamWaitEvent(s_csr, ev_fork, 0);

    deg_zero<<<n_blocks, 256, 0, s_csr>>>(n);
    deg_count<<<e_blocks, 256, 0, s_csr>>>(ei, E);
    scan1<<<nb_scan, 1024, 0, s_csr>>>(n);

    dual_gemm_wreg<<<NSM, 512>>>(x, Wl1, Wr1, 0, n);   // 4th submission

    scan3<<<n_blocks, 256, 0, s_csr>>>(n, E, nb_scan);
    scatter<<<e_blocks, 256, 0, s_csr>>>(ei, E);
    cudaEventRecord(ev_join, s_csr);

    cudaStreamWaitEvent(0, ev_join, 0);

    // ---- layer 1 ----
    gat_layer<<<gat_blocks, 256>>>(att1, b1, 1, n);

    // ---- layer 2 ----
    dual_gemm_wreg<<<NSM, 512>>>(nullptr, Wl2, Wr2, 1, n);
    gat_layer<<<gat_blocks, 256>>>(att2, nullptr, 0, n);

    // ---- fc ----
    fc_out<<<fc_blocks, 256>>>(Wfc, bfc, b2, out, n);
}

// round 14
// speedup vs baseline: 1.1730x; 1.1730x over previous
#include <cuda_runtime.h>
#include <cuda_bf16.h>
#include <mma.h>

using namespace nvcuda;

#define MAXN 50000
#define MAXE 800000
#define NSM  148
#define SW   136          // padded smem row stride (bf16 elems)

// ---------------- scratch (device globals; no allocation allowed) ----------
__device__ float g_xl[MAXN * 128];
__device__ float g_xr[MAXN * 128];
__device__ float g_h [MAXN * 128];
__device__ int   g_deg[MAXN];
__device__ int   g_rowptr[MAXN + 1];
__device__ int   g_blocksum[64];
__device__ int   g_csr_src[MAXE];

// ================= CSR build (by dst) ======================================
__global__ void deg_zero(int n) {
    int i = blockIdx.x * blockDim.x + threadIdx.x;
    if (i < n) g_deg[i] = 0;
}

__global__ void deg_count(const int* __restrict__ ei, int E) {
    int i = blockIdx.x * blockDim.x + threadIdx.x;
    if (i < E) atomicAdd(&g_deg[__ldg(&ei[E + i])], 1);
}

__global__ void scan1(int n) {
    __shared__ int s[1024];
    int i = blockIdx.x * 1024 + threadIdx.x;
    int v = (i < n) ? g_deg[i] : 0;
    s[threadIdx.x] = v;
    __syncthreads();
    #pragma unroll
    for (int off = 1; off < 1024; off <<= 1) {
        int t = (threadIdx.x >= off) ? s[threadIdx.x - off] : 0;
        __syncthreads();
        s[threadIdx.x] += t;
        __syncthreads();
    }
    if (i < n) g_rowptr[i] = s[threadIdx.x] - v;
    if (threadIdx.x == 1023) g_blocksum[blockIdx.x] = s[1023];
}

__global__ void scan3(int n, int E, int nb) {
    __shared__ int bs[64];
    int tid = threadIdx.x;
    if (tid < 64) bs[tid] = (tid < nb) ? g_blocksum[tid] : 0;
    __syncthreads();
    #pragma unroll
    for (int off = 1; off < 64; off <<= 1) {
        int t = (tid < 64 && tid >= off) ? bs[tid - off] : 0;
        __syncthreads();
        if (tid < 64) bs[tid] += t;
        __syncthreads();
    }
    int i = blockIdx.x * blockDim.x + tid;
    if (i < n) {
        int b = i >> 10;
        int pre = (b == 0) ? 0 : bs[b - 1];
        g_rowptr[i] += pre;
        g_deg[i] = 0;
    }
    if (i == 0) g_rowptr[n] = E;
}

__global__ void scatter(const int* __restrict__ ei, int E) {
    int i = blockIdx.x * blockDim.x + threadIdx.x;
    if (i >= E) return;
    int s = __ldg(&ei[i]);
    int d = __ldg(&ei[E + i]);
    int pos = g_rowptr[d] + atomicAdd(&g_deg[d], 1);
    g_csr_src[pos] = s;
}

// ============ persistent dual GEMM, W register-resident (bf16 x3) ==========
// R11 structure: two syncs/chunk, register prefetch of next chunk's A.
using fA = wmma::fragment<wmma::matrix_a, 16, 16, 16, __nv_bfloat16, wmma::row_major>;
using fB = wmma::fragment<wmma::matrix_b, 16, 16, 16, __nv_bfloat16, wmma::row_major>;
using fC = wmma::fragment<wmma::accumulator, 16, 16, 16, float>;

__device__ __forceinline__ void cvt4(float4 v, __nv_bfloat16* hi, __nv_bfloat16* lo) {
    __nv_bfloat16 h0 = __float2bfloat16(v.x);
    __nv_bfloat16 h1 = __float2bfloat16(v.y);
    __nv_bfloat16 h2 = __float2bfloat16(v.z);
    __nv_bfloat16 h3 = __float2bfloat16(v.w);
    hi[0] = h0; hi[1] = h1; hi[2] = h2; hi[3] = h3;
    lo[0] = __float2bfloat16(v.x - __bfloat162float(h0));
    lo[1] = __float2bfloat16(v.y - __bfloat162float(h1));
    lo[2] = __float2bfloat16(v.z - __bfloat162float(h2));
    lo[3] = __float2bfloat16(v.w - __bfloat162float(h3));
}

__global__ void __launch_bounds__(512, 1)
dual_gemm_wreg(const float* __restrict__ Aext,
               const float* __restrict__ Wl,
               const float* __restrict__ Wr,
               int useH, int n) {
    __shared__ __align__(16) unsigned char smem_u[34816];
    __nv_bfloat16* ws   = (__nv_bfloat16*)smem_u;
    __nv_bfloat16* ah_s = (__nv_bfloat16*)smem_u;
    __nv_bfloat16* al_s = ah_s + 32 * SW;

    const float* A = useH ? g_h : Aext;
    const float* Wmat[2] = {Wl, Wr};
    int tid   = threadIdx.x;
    int warp  = tid >> 5;
    int mat   = warp >> 3;          // 0 = xl, 1 = xr
    int sbase = (warp & 7) * 16;

    int r0A = tid >> 5,          c0A = (tid & 31) * 4;
    int r1A = (tid + 512) >> 5,  c1A = (tid & 31) * 4;

    fB wf[2][8];
    #pragma unroll
    for (int m = 0; m < 2; ++m) {
        #pragma unroll
        for (int part = 0; part < 2; ++part) {
            __syncthreads();
            #pragma unroll
            for (int t = 0; t < 8; ++t) {
                int f  = tid + t * 512;
                int r  = f >> 5;
                int c4 = (f & 31) * 4;
                float4 v = *(const float4*)&Wmat[m][(size_t)r * 128 + c4];
                __nv_bfloat16 b0 = __float2bfloat16(v.x);
                __nv_bfloat16 b1 = __float2bfloat16(v.y);
                __nv_bfloat16 b2 = __float2bfloat16(v.z);
                __nv_bfloat16 b3 = __float2bfloat16(v.w);
                __nv_bfloat16* dst = &ws[r * SW + c4];
                if (part == 0) {
                    dst[0] = b0; dst[1] = b1; dst[2] = b2; dst[3] = b3;
                } else {
                    dst[0] = __float2bfloat16(v.x - __bfloat162float(b0));
                    dst[1] = __float2bfloat16(v.y - __bfloat162float(b1));
                    dst[2] = __float2bfloat16(v.z - __bfloat162float(b2));
                    dst[3] = __float2bfloat16(v.w - __bfloat162float(b3));
                }
            }
            __syncthreads();
            if (mat == m) {
                #pragma unroll
                for (int k = 0; k < 8; ++k)
                    wmma::load_matrix_sync(wf[part][k],
                                           &ws[k * 16 * SW + sbase], SW);
            }
        }
    }

    float* C = mat ? g_xr : g_xl;
    int nchunks = (n + 31) >> 5;

    int c = blockIdx.x;
    float4 rv0 = make_float4(0.f, 0.f, 0.f, 0.f);
    float4 rv1 = make_float4(0.f, 0.f, 0.f, 0.f);
    if (c < nchunks) {
        int row0 = c * 32;
        if (row0 + r0A < n) rv0 = *(const float4*)&A[(size_t)(row0 + r0A) * 128 + c0A];
        if (row0 + r1A < n) rv1 = *(const float4*)&A[(size_t)(row0 + r1A) * 128 + c1A];
    }

    for (; c < nchunks; c += gridDim.x) {
        int row0 = c * 32;
        __syncthreads();
        cvt4(rv0, &ah_s[r0A * SW + c0A], &al_s[r0A * SW + c0A]);
        cvt4(rv1, &ah_s[r1A * SW + c1A], &al_s[r1A * SW + c1A]);
        __syncthreads();

        int cn = c + gridDim.x;
        rv0 = make_float4(0.f, 0.f, 0.f, 0.f);
        rv1 = make_float4(0.f, 0.f, 0.f, 0.f);
        if (cn < nchunks) {
            int rown = cn * 32;
            if (rown + r0A < n) rv0 = *(const float4*)&A[(size_t)(rown + r0A) * 128 + c0A];
            if (rown + r1A < n) rv1 = *(const float4*)&A[(size_t)(rown + r1A) * 128 + c1A];
        }

        fC acc[2];
        wmma::fill_fragment(acc[0], 0.0f);
        wmma::fill_fragment(acc[1], 0.0f);

        #pragma unroll
        for (int k = 0; k < 8; ++k) {
            fA ah[2], al[2];
            wmma::load_matrix_sync(ah[0], &ah_s[0 * SW + k * 16], SW);
            wmma::load_matrix_sync(ah[1], &ah_s[16 * SW + k * 16], SW);
            wmma::load_matrix_sync(al[0], &al_s[0 * SW + k * 16], SW);
            wmma::load_matrix_sync(al[1], &al_s[16 * SW + k * 16], SW);
            wmma::mma_sync(acc[0], ah[0], wf[0][k], acc[0]);
            wmma::mma_sync(acc[1], ah[1], wf[0][k], acc[1]);
            wmma::mma_sync(acc[0], ah[0], wf[1][k], acc[0]);
            wmma::mma_sync(acc[1], ah[1], wf[1][k], acc[1]);
            wmma::mma_sync(acc[0], al[0], wf[0][k], acc[0]);
            wmma::mma_sync(acc[1], al[1], wf[0][k], acc[1]);
        }

        #pragma unroll
        for (int rt = 0; rt < 2; ++rt) {
            int wrow0 = row0 + rt * 16;
            if (wrow0 < n)
                wmma::store_matrix_sync(&C[(size_t)wrow0 * 128 + sbase],
                                        acc[rt], 128, wmma::mem_row_major);
        }
    }
}

// ================= fused GAT layer: warp per dst node ======================
__device__ __forceinline__ float edge_p(float4 l4, float4 r4, float4 a4) {
    float v0 = l4.x + r4.x; v0 = v0 > 0.f ? v0 : 0.2f * v0;
    float v1 = l4.y + r4.y; v1 = v1 > 0.f ? v1 : 0.2f * v1;
    float v2 = l4.z + r4.z; v2 = v2 > 0.f ? v2 : 0.2f * v2;
    float v3 = l4.w + r4.w; v3 = v3 > 0.f ? v3 : 0.2f * v3;
    float part = v0 * a4.x + v1 * a4.y + v2 * a4.z + v3 * a4.w;
    part += __shfl_xor_sync(0xffffffffu, part, 1);
    part += __shfl_xor_sync(0xffffffffu, part, 2);
    return __expf(part);
}

__global__ void gat_layer(const float* __restrict__ att,
                          const float* __restrict__ bias,
                          int doRelu, int n) {
    int d = blockIdx.x * 8 + (threadIdx.x >> 5);
    if (d >= n) return;
    int lane = threadIdx.x & 31;

    float4 a4 = *(const float4*)&att[lane * 4];
    float4 r4 = *(const float4*)&g_xr[(size_t)d * 128 + lane * 4];

    // self loop
    float4 l4 = *(const float4*)&g_xl[(size_t)d * 128 + lane * 4];
    float p = edge_p(l4, r4, a4);
    float4 acc = make_float4(p * l4.x, p * l4.y, p * l4.z, p * l4.w);
    float den = p;

    int e0  = g_rowptr[d];
    int end = g_rowptr[d + 1];

    // lane-parallel index preload: one coalesced load covers up to 32 edges
    int myidx = (e0 + lane < end) ? __ldg(&g_csr_src[e0 + lane]) : 0;
    int nb = end - e0; if (nb > 32) nb = 32;

    int j = 0;
    for (; j + 3 < nb; j += 4) {
        int s0 = __shfl_sync(0xffffffffu, myidx, j);
        int s1 = __shfl_sync(0xffffffffu, myidx, j + 1);
        int s2 = __shfl_sync(0xffffffffu, myidx, j + 2);
        int s3 = __shfl_sync(0xffffffffu, myidx, j + 3);
        float4 u0 = *(const float4*)&g_xl[(size_t)s0 * 128 + lane * 4];
        float4 u1 = *(const float4*)&g_xl[(size_t)s1 * 128 + lane * 4];
        float4 u2 = *(const float4*)&g_xl[(size_t)s2 * 128 + lane * 4];
        float4 u3 = *(const float4*)&g_xl[(size_t)s3 * 128 + lane * 4];
        float p0 = edge_p(u0, r4, a4);
        float p1 = edge_p(u1, r4, a4);
        float p2 = edge_p(u2, r4, a4);
        float p3 = edge_p(u3, r4, a4);
        acc.x += p0 * u0.x + p1 * u1.x + p2 * u2.x + p3 * u3.x;
        acc.y += p0 * u0.y + p1 * u1.y + p2 * u2.y + p3 * u3.y;
        acc.z += p0 * u0.z + p1 * u1.z + p2 * u2.z + p3 * u3.z;
        acc.w += p0 * u0.w + p1 * u1.w + p2 * u2.w + p3 * u3.w;
        den += p0 + p1 + p2 + p3;
    }
    for (; j < nb; ++j) {
        int s0 = __shfl_sync(0xffffffffu, myidx, j);
        float4 u0 = *(const float4*)&g_xl[(size_t)s0 * 128 + lane * 4];
        float p0 = edge_p(u0, r4, a4);
        acc.x += p0 * u0.x; acc.y += p0 * u0.y;
        acc.z += p0 * u0.z; acc.w += p0 * u0.w;
        den += p0;
    }
    // rare tail: degree > 32
    for (int e = e0 + 32; e < end; ++e) {
        int s0 = __ldg(&g_csr_src[e]);
        float4 u0 = *(const float4*)&g_xl[(size_t)s0 * 128 + lane * 4];
        float p0 = edge_p(u0, r4, a4);
        acc.x += p0 * u0.x; acc.y += p0 * u0.y;
        acc.z += p0 * u0.z; acc.w += p0 * u0.w;
        den += p0;
    }

    float inv = 1.0f / (den + 1e-16f);
    float4 b4 = bias ? *(const float4*)&bias[lane * 4]
                     : make_float4(0.f, 0.f, 0.f, 0.f);
    float4 o;
    o.x = acc.x * inv + b4.x;
    o.y = acc.y * inv + b4.y;
    o.z = acc.z * inv + b4.z;
    o.w = acc.w * inv + b4.w;
    if (doRelu) {
        o.x = o.x > 0.f ? o.x : 0.f;
        o.y = o.y > 0.f ? o.y : 0.f;
        o.z = o.z > 0.f ? o.z : 0.f;
        o.w = o.w > 0.f ? o.w : 0.f;
    }
    *(float4*)&g_h[(size_t)d * 128 + lane * 4] = o;
}

// ============ final fc: thread per node, out = relu(h+b2) @ Wfc + bfc ======
__global__ void fc_out(const float* __restrict__ Wfc,
                       const float* __restrict__ bfc,
                       const float* __restrict__ b2,
                       float* __restrict__ out, int n) {
    __shared__ float Ws[128 * 10];
    __shared__ float bs[16];
    __shared__ float b2s[128];
    for (int i = threadIdx.x; i < 1280; i += blockDim.x) Ws[i] = Wfc[i];
    if (threadIdx.x < 10)  bs[threadIdx.x]  = bfc[threadIdx.x];
    if (threadIdx.x < 128) b2s[threadIdx.x] = b2[threadIdx.x];
    __syncthreads();
    int node = blockIdx.x * blockDim.x + threadIdx.x;
    if (node >= n) return;
    const float* hrow = &g_h[(size_t)node * 128];
    float acc[10];
    #pragma unroll
    for (int c = 0; c < 10; ++c) acc[c] = bs[c];
    #pragma unroll
    for (int k4 = 0; k4 < 128; k4 += 4) {
        float4 hv4 = *(const float4*)&hrow[k4];
        float h0 = hv4.x + b2s[k4];     h0 = h0 > 0.f ? h0 : 0.f;
        float h1 = hv4.y + b2s[k4 + 1]; h1 = h1 > 0.f ? h1 : 0.f;
        float h2 = hv4.z + b2s[k4 + 2]; h2 = h2 > 0.f ? h2 : 0.f;
        float h3 = hv4.w + b2s[k4 + 3]; h3 = h3 > 0.f ? h3 : 0.f;
        #pragma unroll
        for (int c = 0; c < 10; ++c)
            acc[c] += h0 * Ws[(k4)     * 10 + c]
                    + h1 * Ws[(k4 + 1) * 10 + c]
                    + h2 * Ws[(k4 + 2) * 10 + c]
                    + h3 * Ws[(k4 + 3) * 10 + c];
    }
    #pragma unroll
    for (int c = 0; c < 10; ++c)
        out[(size_t)node * 10 + c] = acc[c];
}

// ================= launch ==================================================
extern "C" void kernel_launch(void* const* d_in, const int* in_sizes, int n_in,
                              void* d_out, int out_size) {
    const float* x    = (const float*)d_in[0];
    const int*   ei   = (const int*)  d_in[1];
    const float* Wl1  = (const float*)d_in[2];
    const float* Wr1  = (const float*)d_in[3];
    const float* att1 = (const float*)d_in[4];
    const float* b1   = (const float*)d_in[5];
    const float* Wl2  = (const float*)d_in[6];
    const float* Wr2  = (const float*)d_in[7];
    const float* att2 = (const float*)d_in[8];
    const float* b2   = (const float*)d_in[9];
    const float* Wfc  = (const float*)d_in[10];
    const float* bfc  = (const float*)d_in[11];
    float* out = (float*)d_out;

    int n = in_sizes[0] / 128;
    int E = in_sizes[1] / 2;

    int nb_scan    = (n + 1023) / 1024;
    int gat_blocks = (n + 7) / 8;
    int fc_blocks  = (n + 255) / 256;
    int e_blocks   = (E + 255) / 256;
    int n_blocks   = (n + 255) / 256;

    static int inited = 0;
    static cudaStream_t s_csr;
    static cudaEvent_t  ev_fork, ev_join;
    if (!inited) {
        cudaStreamCreateWithFlags(&s_csr, cudaStreamNonBlocking);
        cudaEventCreateWithFlags(&ev_fork, cudaEventDisableTiming);
        cudaEventCreateWithFlags(&ev_join, cudaEventDisableTiming);
        inited = 1;
    }

    // ---- fork: CSR build (s_csr)  ||  layer-1 GEMM (default) ----
    // (dual_gemm submitted 4th so the ncu slot profiles it)
    cudaEventRecord(ev_fork, 0);
    cudaStreamWaitEvent(s_csr, ev_fork, 0);

    deg_zero<<<n_blocks, 256, 0, s_csr>>>(n);
    deg_count<<<e_blocks, 256, 0, s_csr>>>(ei, E);
    scan1<<<nb_scan, 1024, 0, s_csr>>>(n);

    dual_gemm_wreg<<<NSM, 512>>>(x, Wl1, Wr1, 0, n);   // 4th submission

    scan3<<<n_blocks, 256, 0, s_csr>>>(n, E, nb_scan);
    scatter<<<e_blocks, 256, 0, s_csr>>>(ei, E);
    cudaEventRecord(ev_join, s_csr);

    cudaStreamWaitEvent(0, ev_join, 0);

    // ---- layer 1 ----
    gat_layer<<<gat_blocks, 256>>>(att1, b1, 1, n);

    // ---- layer 2 ----
    dual_gemm_wreg<<<NSM, 512>>>(nullptr, Wl2, Wr2, 1, n);
    gat_layer<<<gat_blocks, 256>>>(att2, nullptr, 0, n);

    // ---- fc ----
    fc_out<<<fc_blocks, 256>>>(Wfc, bfc, b2, out, n);
}

// round 15
// speedup vs baseline: 1.1816x; 1.0073x over previous
#include <cuda_runtime.h>
#include <cuda_bf16.h>
#include <mma.h>

using namespace nvcuda;

#define MAXN 50000
#define MAXE 800000
#define NSM  148
#define SW   136          // padded smem row stride (bf16 elems); row = 272B

// ---------------- scratch (device globals; no allocation allowed) ----------
__device__ float g_xl[MAXN * 128];
__device__ float g_xr[MAXN * 128];
__device__ float g_h [MAXN * 128];
__device__ int   g_deg[MAXN];
__device__ int   g_rowptr[MAXN + 1];
__device__ int   g_blocksum[64];
__device__ int   g_csr_src[MAXE];

// ================= CSR build (by dst) ======================================
__global__ void deg_zero(int n) {
    int i = blockIdx.x * blockDim.x + threadIdx.x;
    if (i < n) g_deg[i] = 0;
}

__global__ void deg_count(const int* __restrict__ ei, int E) {
    int i = blockIdx.x * blockDim.x + threadIdx.x;
    if (i < E) atomicAdd(&g_deg[__ldg(&ei[E + i])], 1);
}

__global__ void scan1(int n) {
    __shared__ int s[1024];
    int i = blockIdx.x * 1024 + threadIdx.x;
    int v = (i < n) ? g_deg[i] : 0;
    s[threadIdx.x] = v;
    __syncthreads();
    #pragma unroll
    for (int off = 1; off < 1024; off <<= 1) {
        int t = (threadIdx.x >= off) ? s[threadIdx.x - off] : 0;
        __syncthreads();
        s[threadIdx.x] += t;
        __syncthreads();
    }
    if (i < n) g_rowptr[i] = s[threadIdx.x] - v;
    if (threadIdx.x == 1023) g_blocksum[blockIdx.x] = s[1023];
}

__global__ void scan3(int n, int E, int nb) {
    __shared__ int bs[64];
    int tid = threadIdx.x;
    if (tid < 64) bs[tid] = (tid < nb) ? g_blocksum[tid] : 0;
    __syncthreads();
    #pragma unroll
    for (int off = 1; off < 64; off <<= 1) {
        int t = (tid < 64 && tid >= off) ? bs[tid - off] : 0;
        __syncthreads();
        if (tid < 64) bs[tid] += t;
        __syncthreads();
    }
    int i = blockIdx.x * blockDim.x + tid;
    if (i < n) {
        int b = i >> 10;
        int pre = (b == 0) ? 0 : bs[b - 1];
        g_rowptr[i] += pre;
        g_deg[i] = 0;
    }
    if (i == 0) g_rowptr[n] = E;
}

__global__ void scatter(const int* __restrict__ ei, int E) {
    int i = blockIdx.x * blockDim.x + threadIdx.x;
    if (i >= E) return;
    int s = __ldg(&ei[i]);
    int d = __ldg(&ei[E + i]);
    int pos = g_rowptr[d] + atomicAdd(&g_deg[d], 1);
    g_csr_src[pos] = s;
}

// ============ persistent dual GEMM, W register-resident (bf16 x3) ==========
// R11 structure (two syncs/chunk, register prefetch) + PACKED 8B smem stores.
using fA = wmma::fragment<wmma::matrix_a, 16, 16, 16, __nv_bfloat16, wmma::row_major>;
using fB = wmma::fragment<wmma::matrix_b, 16, 16, 16, __nv_bfloat16, wmma::row_major>;
using fC = wmma::fragment<wmma::accumulator, 16, 16, 16, float>;

// packed: one uint2 (4 bf16) store for hi, one for lo
__device__ __forceinline__ void cvt4(float4 v, __nv_bfloat16* hi, __nv_bfloat16* lo) {
    __nv_bfloat162 h01 = __floats2bfloat162_rn(v.x, v.y);
    __nv_bfloat162 h23 = __floats2bfloat162_rn(v.z, v.w);
    *(uint2*)hi = make_uint2(*(unsigned*)&h01, *(unsigned*)&h23);
    float2 f01 = __bfloat1622float2(h01);
    float2 f23 = __bfloat1622float2(h23);
    __nv_bfloat162 l01 = __floats2bfloat162_rn(v.x - f01.x, v.y - f01.y);
    __nv_bfloat162 l23 = __floats2bfloat162_rn(v.z - f23.x, v.w - f23.y);
    *(uint2*)lo = make_uint2(*(unsigned*)&l01, *(unsigned*)&l23);
}

__global__ void __launch_bounds__(512, 1)
dual_gemm_wreg(const float* __restrict__ Aext,
               const float* __restrict__ Wl,
               const float* __restrict__ Wr,
               int useH, int n) {
    __shared__ __align__(16) unsigned char smem_u[34816];
    __nv_bfloat16* ws   = (__nv_bfloat16*)smem_u;
    __nv_bfloat16* ah_s = (__nv_bfloat16*)smem_u;
    __nv_bfloat16* al_s = ah_s + 32 * SW;

    const float* A = useH ? g_h : Aext;
    const float* Wmat[2] = {Wl, Wr};
    int tid   = threadIdx.x;
    int warp  = tid >> 5;
    int mat   = warp >> 3;          // 0 = xl, 1 = xr
    int sbase = (warp & 7) * 16;

    int r0A = tid >> 5,          c0A = (tid & 31) * 4;
    int r1A = (tid + 512) >> 5,  c1A = (tid & 31) * 4;

    // ---- load W fragments into registers (4 staging passes, packed STS) ---
    fB wf[2][8];
    #pragma unroll
    for (int m = 0; m < 2; ++m) {
        #pragma unroll
        for (int part = 0; part < 2; ++part) {
            __syncthreads();
            #pragma unroll
            for (int t = 0; t < 8; ++t) {
                int f  = tid + t * 512;
                int r  = f >> 5;
                int c4 = (f & 31) * 4;
                float4 v = *(const float4*)&Wmat[m][(size_t)r * 128 + c4];
                __nv_bfloat162 h01 = __floats2bfloat162_rn(v.x, v.y);
                __nv_bfloat162 h23 = __floats2bfloat162_rn(v.z, v.w);
                if (part == 0) {
                    *(uint2*)&ws[r * SW + c4] =
                        make_uint2(*(unsigned*)&h01, *(unsigned*)&h23);
                } else {
                    float2 f01 = __bfloat1622float2(h01);
                    float2 f23 = __bfloat1622float2(h23);
                    __nv_bfloat162 l01 = __floats2bfloat162_rn(v.x - f01.x, v.y - f01.y);
                    __nv_bfloat162 l23 = __floats2bfloat162_rn(v.z - f23.x, v.w - f23.y);
                    *(uint2*)&ws[r * SW + c4] =
                        make_uint2(*(unsigned*)&l01, *(unsigned*)&l23);
                }
            }
            __syncthreads();
            if (mat == m) {
                #pragma unroll
                for (int k = 0; k < 8; ++k)
                    wmma::load_matrix_sync(wf[part][k],
                                           &ws[k * 16 * SW + sbase], SW);
            }
        }
    }

    float* C = mat ? g_xr : g_xl;
    int nchunks = (n + 31) >> 5;

    int c = blockIdx.x;
    float4 rv0 = make_float4(0.f, 0.f, 0.f, 0.f);
    float4 rv1 = make_float4(0.f, 0.f, 0.f, 0.f);
    if (c < nchunks) {
        int row0 = c * 32;
        if (row0 + r0A < n) rv0 = *(const float4*)&A[(size_t)(row0 + r0A) * 128 + c0A];
        if (row0 + r1A < n) rv1 = *(const float4*)&A[(size_t)(row0 + r1A) * 128 + c1A];
    }

    for (; c < nchunks; c += gridDim.x) {
        int row0 = c * 32;
        __syncthreads();
        cvt4(rv0, &ah_s[r0A * SW + c0A], &al_s[r0A * SW + c0A]);
        cvt4(rv1, &ah_s[r1A * SW + c1A], &al_s[r1A * SW + c1A]);
        __syncthreads();

        int cn = c + gridDim.x;
        rv0 = make_float4(0.f, 0.f, 0.f, 0.f);
        rv1 = make_float4(0.f, 0.f, 0.f, 0.f);
        if (cn < nchunks) {
            int rown = cn * 32;
            if (rown + r0A < n) rv0 = *(const float4*)&A[(size_t)(rown + r0A) * 128 + c0A];
            if (rown + r1A < n) rv1 = *(const float4*)&A[(size_t)(rown + r1A) * 128 + c1A];
        }

        fC acc[2];
        wmma::fill_fragment(acc[0], 0.0f);
        wmma::fill_fragment(acc[1], 0.0f);

        #pragma unroll
        for (int k = 0; k < 8; ++k) {
            fA ah[2], al[2];
            wmma::load_matrix_sync(ah[0], &ah_s[0 * SW + k * 16], SW);
            wmma::load_matrix_sync(ah[1], &ah_s[16 * SW + k * 16], SW);
            wmma::load_matrix_sync(al[0], &al_s[0 * SW + k * 16], SW);
            wmma::load_matrix_sync(al[1], &al_s[16 * SW + k * 16], SW);
            wmma::mma_sync(acc[0], ah[0], wf[0][k], acc[0]);
            wmma::mma_sync(acc[1], ah[1], wf[0][k], acc[1]);
            wmma::mma_sync(acc[0], ah[0], wf[1][k], acc[0]);
            wmma::mma_sync(acc[1], ah[1], wf[1][k], acc[1]);
            wmma::mma_sync(acc[0], al[0], wf[0][k], acc[0]);
            wmma::mma_sync(acc[1], al[1], wf[0][k], acc[1]);
        }

        #pragma unroll
        for (int rt = 0; rt < 2; ++rt) {
            int wrow0 = row0 + rt * 16;
            if (wrow0 < n)
                wmma::store_matrix_sync(&C[(size_t)wrow0 * 128 + sbase],
                                        acc[rt], 128, wmma::mem_row_major);
        }
    }
}

// ================= fused GAT layer: warp per dst node ======================
__device__ __forceinline__ float edge_p(float4 l4, float4 r4, float4 a4) {
    float v0 = l4.x + r4.x; v0 = v0 > 0.f ? v0 : 0.2f * v0;
    float v1 = l4.y + r4.y; v1 = v1 > 0.f ? v1 : 0.2f * v1;
    float v2 = l4.z + r4.z; v2 = v2 > 0.f ? v2 : 0.2f * v2;
    float v3 = l4.w + r4.w; v3 = v3 > 0.f ? v3 : 0.2f * v3;
    float part = v0 * a4.x + v1 * a4.y + v2 * a4.z + v3 * a4.w;
    part += __shfl_xor_sync(0xffffffffu, part, 1);
    part += __shfl_xor_sync(0xffffffffu, part, 2);
    return __expf(part);
}

__global__ void gat_layer(const float* __restrict__ att,
                          const float* __restrict__ bias,
                          int doRelu, int n) {
    int d = blockIdx.x * 8 + (threadIdx.x >> 5);
    if (d >= n) return;
    int lane = threadIdx.x & 31;

    float4 a4 = *(const float4*)&att[lane * 4];
    float4 r4 = *(const float4*)&g_xr[(size_t)d * 128 + lane * 4];

    // self loop
    float4 l4 = *(const float4*)&g_xl[(size_t)d * 128 + lane * 4];
    float p = edge_p(l4, r4, a4);
    float4 acc = make_float4(p * l4.x, p * l4.y, p * l4.z, p * l4.w);
    float den = p;

    int e0  = g_rowptr[d];
    int end = g_rowptr[d + 1];

    // lane-parallel index preload: one coalesced load covers up to 32 edges
    int myidx = (e0 + lane < end) ? __ldg(&g_csr_src[e0 + lane]) : 0;
    int nb = end - e0; if (nb > 32) nb = 32;

    int j = 0;
    for (; j + 3 < nb; j += 4) {
        int s0 = __shfl_sync(0xffffffffu, myidx, j);
        int s1 = __shfl_sync(0xffffffffu, myidx, j + 1);
        int s2 = __shfl_sync(0xffffffffu, myidx, j + 2);
        int s3 = __shfl_sync(0xffffffffu, myidx, j + 3);
        float4 u0 = *(const float4*)&g_xl[(size_t)s0 * 128 + lane * 4];
        float4 u1 = *(const float4*)&g_xl[(size_t)s1 * 128 + lane * 4];
        float4 u2 = *(const float4*)&g_xl[(size_t)s2 * 128 + lane * 4];
        float4 u3 = *(const float4*)&g_xl[(size_t)s3 * 128 + lane * 4];
        float p0 = edge_p(u0, r4, a4);
        float p1 = edge_p(u1, r4, a4);
        float p2 = edge_p(u2, r4, a4);
        float p3 = edge_p(u3, r4, a4);
        acc.x += p0 * u0.x + p1 * u1.x + p2 * u2.x + p3 * u3.x;
        acc.y += p0 * u0.y + p1 * u1.y + p2 * u2.y + p3 * u3.y;
        acc.z += p0 * u0.z + p1 * u1.z + p2 * u2.z + p3 * u3.z;
        acc.w += p0 * u0.w + p1 * u1.w + p2 * u2.w + p3 * u3.w;
        den += p0 + p1 + p2 + p3;
    }
    for (; j < nb; ++j) {
        int s0 = __shfl_sync(0xffffffffu, myidx, j);
        float4 u0 = *(const float4*)&g_xl[(size_t)s0 * 128 + lane * 4];
        float p0 = edge_p(u0, r4, a4);
        acc.x += p0 * u0.x; acc.y += p0 * u0.y;
        acc.z += p0 * u0.z; acc.w += p0 * u0.w;
        den += p0;
    }
    // rare tail: degree > 32
    for (int e = e0 + 32; e < end; ++e) {
        int s0 = __ldg(&g_csr_src[e]);
        float4 u0 = *(const float4*)&g_xl[(size_t)s0 * 128 + lane * 4];
        float p0 = edge_p(u0, r4, a4);
        acc.x += p0 * u0.x; acc.y += p0 * u0.y;
        acc.z += p0 * u0.z; acc.w += p0 * u0.w;
        den += p0;
    }

    float inv = 1.0f / (den + 1e-16f);
    float4 b4 = bias ? *(const float4*)&bias[lane * 4]
                     : make_float4(0.f, 0.f, 0.f, 0.f);
    float4 o;
    o.x = acc.x * inv + b4.x;
    o.y = acc.y * inv + b4.y;
    o.z = acc.z * inv + b4.z;
    o.w = acc.w * inv + b4.w;
    if (doRelu) {
        o.x = o.x > 0.f ? o.x : 0.f;
        o.y = o.y > 0.f ? o.y : 0.f;
        o.z = o.z > 0.f ? o.z : 0.f;
        o.w = o.w > 0.f ? o.w : 0.f;
    }
    *(float4*)&g_h[(size_t)d * 128 + lane * 4] = o;
}

// ============ final fc: thread per node, out = relu(h+b2) @ Wfc + bfc ======
__global__ void fc_out(const float* __restrict__ Wfc,
                       const float* __restrict__ bfc,
                       const float* __restrict__ b2,
                       float* __restrict__ out, int n) {
    __shared__ float Ws[128 * 10];
    __shared__ float bs[16];
    __shared__ float b2s[128];
    for (int i = threadIdx.x; i < 1280; i += blockDim.x) Ws[i] = Wfc[i];
    if (threadIdx.x < 10)  bs[threadIdx.x]  = bfc[threadIdx.x];
    if (threadIdx.x < 128) b2s[threadIdx.x] = b2[threadIdx.x];
    __syncthreads();
    int node = blockIdx.x * blockDim.x + threadIdx.x;
    if (node >= n) return;
    const float* hrow = &g_h[(size_t)node * 128];
    float acc[10];
    #pragma unroll
    for (int c = 0; c < 10; ++c) acc[c] = bs[c];
    #pragma unroll
    for (int k4 = 0; k4 < 128; k4 += 4) {
        float4 hv4 = *(const float4*)&hrow[k4];
        float h0 = hv4.x + b2s[k4];     h0 = h0 > 0.f ? h0 : 0.f;
        float h1 = hv4.y + b2s[k4 + 1]; h1 = h1 > 0.f ? h1 : 0.f;
        float h2 = hv4.z + b2s[k4 + 2]; h2 = h2 > 0.f ? h2 : 0.f;
        float h3 = hv4.w + b2s[k4 + 3]; h3 = h3 > 0.f ? h3 : 0.f;
        #pragma unroll
        for (int c = 0; c < 10; ++c)
            acc[c] += h0 * Ws[(k4)     * 10 + c]
                    + h1 * Ws[(k4 + 1) * 10 + c]
                    + h2 * Ws[(k4 + 2) * 10 + c]
                    + h3 * Ws[(k4 + 3) * 10 + c];
    }
    #pragma unroll
    for (int c = 0; c < 10; ++c)
        out[(size_t)node * 10 + c] = acc[c];
}

// ================= launch ==================================================
extern "C" void kernel_launch(void* const* d_in, const int* in_sizes, int n_in,
                              void* d_out, int out_size) {
    const float* x    = (const float*)d_in[0];
    const int*   ei   = (const int*)  d_in[1];
    const float* Wl1  = (const float*)d_in[2];
    const float* Wr1  = (const float*)d_in[3];
    const float* att1 = (const float*)d_in[4];
    const float* b1   = (const float*)d_in[5];
    const float* Wl2  = (const float*)d_in[6];
    const float* Wr2  = (const float*)d_in[7];
    const float* att2 = (const float*)d_in[8];
    const float* b2   = (const float*)d_in[9];
    const float* Wfc  = (const float*)d_in[10];
    const float* bfc  = (const float*)d_in[11];
    float* out = (float*)d_out;

    int n = in_sizes[0] / 128;
    int E = in_sizes[1] / 2;

    int nb_scan    = (n + 1023) / 1024;
    int gat_blocks = (n + 7) / 8;
    int fc_blocks  = (n + 255) / 256;
    int e_blocks   = (E + 255) / 256;
    int n_blocks   = (n + 255) / 256;

    static int inited = 0;
    static cudaStream_t s_csr;
    static cudaEvent_t  ev_fork, ev_join;
    if (!inited) {
        cudaStreamCreateWithFlags(&s_csr, cudaStreamNonBlocking);
        cudaEventCreateWithFlags(&ev_fork, cudaEventDisableTiming);
        cudaEventCreateWithFlags(&ev_join, cudaEventDisableTiming);
        inited = 1;
    }

    // ---- fork: CSR build (s_csr)  ||  layer-1 GEMM (default) ----
    // (dual_gemm submitted 4th so the ncu slot profiles it)
    cudaEventRecord(ev_fork, 0);
    cudaStreamWaitEvent(s_csr, ev_fork, 0);

    deg_zero<<<n_blocks, 256, 0, s_csr>>>(n);
    deg_count<<<e_blocks, 256, 0, s_csr>>>(ei, E);
    scan1<<<nb_scan, 1024, 0, s_csr>>>(n);

    dual_gemm_wreg<<<NSM, 512>>>(x, Wl1, Wr1, 0, n);   // 4th submission

    scan3<<<n_blocks, 256, 0, s_csr>>>(n, E, nb_scan);
    scatter<<<e_blocks, 256, 0, s_csr>>>(ei, E);
    cudaEventRecord(ev_join, s_csr);

    cudaStreamWaitEvent(0, ev_join, 0);

    // ---- layer 1 ----
    gat_layer<<<gat_blocks, 256>>>(att1, b1, 1, n);

    // ---- layer 2 ----
    dual_gemm_wreg<<<NSM, 512>>>(nullptr, Wl2, Wr2, 1, n);
    gat_layer<<<gat_blocks, 256>>>(att2, nullptr, 0, n);

    // ---- fc ----
    fc_out<<<fc_blocks, 256>>>(Wfc, bfc, b2, out, n);
}